// round 4
// baseline (speedup 1.0000x reference)
#include <cuda_runtime.h>
#include <cuda_bf16.h>
#include <cfloat>
#include <stdint.h>
#include <math.h>

#define NB 16384
#define NKEY 8192
#define ND 1024
#define BM 64
#define BN 256
#define BK 32
#define STAGES 4
#define NTILE (NKEY / BN)          // 32 key tiles
#define KSTEPS (ND / BK)           // 32 k-steps per tile
#define NSTEP (NTILE * KSTEPS)     // 1024
#define NCAND 8
#define THREADS 256

#define ROWB 80                    // padded row stride (64B data + 16B pad)
#define A_BYTES (BM * ROWB)        // 5120
#define B_BYTES (BN * ROWB)        // 20480
#define STAGE_BYTES (A_BYTES + B_BYTES)   // 25600
#define SMEM_BYTES (STAGES * STAGE_BYTES) // 102400  -> 2 CTAs/SM

// ---------------- scratch ----------------
__device__ __nv_bfloat16 g_qn16[(size_t)NB * ND];
__device__ __nv_bfloat16 g_kn16[(size_t)NKEY * ND];
__device__ float g_qinv[NB];
__device__ float g_kinv[NKEY];
__device__ int   g_cand[NB * NCAND];

// ---------------- helpers ----------------
static __device__ __forceinline__ uint32_t smem_u32(const void* p) {
    return (uint32_t)__cvta_generic_to_shared(p);
}
static __device__ __forceinline__ void cp16(uint32_t dst, const void* src) {
    asm volatile("cp.async.cg.shared.global [%0], [%1], 16;" :: "r"(dst), "l"(src));
}
static __device__ __forceinline__ void cp_commit() {
    asm volatile("cp.async.commit_group;" ::: "memory");
}
static __device__ __forceinline__ void cp_wait2() {
    asm volatile("cp.async.wait_group 2;" ::: "memory");
}
static __device__ __forceinline__ void ldm_x4(uint32_t* r, uint32_t a) {
    asm volatile("ldmatrix.sync.aligned.m8n8.x4.shared.b16 {%0,%1,%2,%3}, [%4];"
                 : "=r"(r[0]), "=r"(r[1]), "=r"(r[2]), "=r"(r[3]) : "r"(a));
}
static __device__ __forceinline__ void mma16816(float* d, const uint32_t* a,
                                                const uint32_t* b) {
    asm volatile(
        "mma.sync.aligned.m16n8k16.row.col.f32.bf16.bf16.f32 "
        "{%0,%1,%2,%3}, {%4,%5,%6,%7}, {%8,%9}, {%0,%1,%2,%3};"
        : "+f"(d[0]), "+f"(d[1]), "+f"(d[2]), "+f"(d[3])
        : "r"(a[0]), "r"(a[1]), "r"(a[2]), "r"(a[3]), "r"(b[0]), "r"(b[1]));
}

// ---------------- normalize -> bf16 (+ inverse norms) ----------------
__global__ void norm_kernel(const float* __restrict__ in, int which) {
    __nv_bfloat16* out = which ? g_kn16 : g_qn16;
    float* invp = which ? g_kinv : g_qinv;
    int row = blockIdx.x;
    int t = threadIdx.x;  // 256 threads, one float4 each
    float4 v = reinterpret_cast<const float4*>(in)[(size_t)row * (ND / 4) + t];
    float ss = v.x * v.x + v.y * v.y + v.z * v.z + v.w * v.w;
    #pragma unroll
    for (int o = 16; o; o >>= 1) ss += __shfl_xor_sync(0xffffffffu, ss, o);
    __shared__ float wsum[8];
    if ((t & 31) == 0) wsum[t >> 5] = ss;
    __syncthreads();
    float tot = 0.0f;
    #pragma unroll
    for (int i = 0; i < 8; ++i) tot += wsum[i];
    float inv = 1.0f / fmaxf(sqrtf(tot), 1e-12f);
    if (t == 0) invp[row] = inv;
    union { __nv_bfloat162 h2[2]; uint2 u; } pk;
    pk.h2[0] = __floats2bfloat162_rn(v.x * inv, v.y * inv);
    pk.h2[1] = __floats2bfloat162_rn(v.z * inv, v.w * inv);
    reinterpret_cast<uint2*>(out)[(size_t)row * (ND / 4) + t] = pk.u;
}

// ---------------- top-4 insert ----------------
static __device__ __forceinline__ void top4_insert(float* tv, int* ti, float v, int idx) {
    if (v > tv[3]) {
        tv[3] = v; ti[3] = idx;
        #pragma unroll
        for (int s = 3; s > 0; --s) {
            if (tv[s] > tv[s - 1]) {
                float tf = tv[s]; tv[s] = tv[s - 1]; tv[s - 1] = tf;
                int tn = ti[s]; ti[s] = ti[s - 1]; ti[s - 1] = tn;
            }
        }
    }
}

// ---------------- bf16 sim GEMM (mma.sync) + streaming top-4/slice ----------------
__global__ __launch_bounds__(THREADS, 2) void simtopk_kernel() {
    extern __shared__ char dynsmem[];
    const uint32_t sbase = smem_u32(dynsmem);
    const int tid = threadIdx.x;
    const int wid = tid >> 5, lane = tid & 31;
    const int warp_m = wid & 1;     // 0..1 -> rows warp_m*32
    const int warp_n = wid >> 1;    // 0..3 -> cols warp_n*64
    const int qbase = blockIdx.x * BM;

    float acc[2][8][4];
    float tv[4][4]; int ti[4][4];
    #pragma unroll
    for (int mf = 0; mf < 2; ++mf)
        #pragma unroll
        for (int nf = 0; nf < 8; ++nf)
            #pragma unroll
            for (int e = 0; e < 4; ++e) acc[mf][nf][e] = 0.0f;
    #pragma unroll
    for (int r = 0; r < 4; ++r)
        #pragma unroll
        for (int e = 0; e < 4; ++e) { tv[r][e] = -FLT_MAX; ti[r][e] = 0; }

    auto issue_loads = [&](int j) {
        const int stage = j & 3;
        const int ks = j & 31, kt = j >> 5;
        const int kcol = ks * BK;
        const uint32_t aS = sbase + stage * STAGE_BYTES;
        const uint32_t bS = aS + A_BYTES;
        {   // A: 64 rows x 4 chunks of 16B; row = tid&63 keeps banks conflict-free
            int row = tid & 63, c = tid >> 6;
            cp16(aS + row * ROWB + c * 16,
                 g_qn16 + (size_t)(qbase + row) * ND + kcol + c * 8);
        }
        #pragma unroll
        for (int u = 0; u < 4; ++u) {   // B: 256 rows x 4 chunks
            cp16(bS + tid * ROWB + u * 16,
                 g_kn16 + (size_t)(kt * BN + tid) * ND + kcol + u * 8);
        }
    };

    #pragma unroll
    for (int j = 0; j < STAGES - 1; ++j) { issue_loads(j); cp_commit(); }

    for (int i = 0; i < NSTEP; ++i) {
        cp_wait2();
        __syncthreads();     // stage i visible to all; stage i-1 free for overwrite
        if (i + 3 < NSTEP) issue_loads(i + 3);
        cp_commit();

        const uint32_t aS = sbase + (i & 3) * STAGE_BYTES;
        const uint32_t bS = aS + A_BYTES;
        const uint32_t aAddr = aS + (warp_m * 32 + (lane & 15)) * ROWB + (lane >> 4) * 16;
        const uint32_t bAddr = bS + (warp_n * 64 + (lane & 7) + (lane >> 4) * 8) * ROWB
                               + ((lane >> 3) & 1) * 16;
        #pragma unroll
        for (int kf = 0; kf < 2; ++kf) {
            uint32_t af[2][4];
            ldm_x4(af[0], aAddr + kf * 32);
            ldm_x4(af[1], aAddr + 16 * ROWB + kf * 32);
            #pragma unroll
            for (int ng = 0; ng < 4; ++ng) {
                uint32_t bf[4];
                ldm_x4(bf, bAddr + ng * 16 * ROWB + kf * 32);
                mma16816(acc[0][2 * ng],     af[0], bf + 0);
                mma16816(acc[0][2 * ng + 1], af[0], bf + 2);
                mma16816(acc[1][2 * ng],     af[1], bf + 0);
                mma16816(acc[1][2 * ng + 1], af[1], bf + 2);
            }
        }

        if ((i & 31) == 31) {   // key tile done: fold sims into per-slice top-4
            const int cb = (i >> 5) * BN + warp_n * 64 + (lane & 3) * 2;
            #pragma unroll
            for (int mf = 0; mf < 2; ++mf)
                #pragma unroll
                for (int nf = 0; nf < 8; ++nf) {
                    float* a4 = acc[mf][nf];
                    const int c0 = cb + nf * 8;
                    top4_insert(tv[mf * 2],     ti[mf * 2],     a4[0], c0);
                    top4_insert(tv[mf * 2],     ti[mf * 2],     a4[1], c0 + 1);
                    top4_insert(tv[mf * 2 + 1], ti[mf * 2 + 1], a4[2], c0);
                    top4_insert(tv[mf * 2 + 1], ti[mf * 2 + 1], a4[3], c0 + 1);
                    a4[0] = a4[1] = a4[2] = a4[3] = 0.0f;
                }
        }
    }

    // ---------------- merge: 16 slices x top-4 -> top-8 per row ----------------
    __syncthreads();
    float* sv = reinterpret_cast<float*>(dynsmem);            // [64][16][4]
    int* sidx = reinterpret_cast<int*>(dynsmem + 16384);      // [64][16][4]
    #pragma unroll
    for (int rp = 0; rp < 4; ++rp) {
        int row = warp_m * 32 + (rp >> 1) * 16 + (rp & 1) * 8 + (lane >> 2);
        int slice = warp_n * 4 + (lane & 3);
        #pragma unroll
        for (int e = 0; e < 4; ++e) {
            sv[(row * 16 + slice) * 4 + e] = tv[rp][e];
            sidx[(row * 16 + slice) * 4 + e] = ti[rp][e];
        }
    }
    __syncthreads();
    if (tid < BM) {
        const int row = tid;
        const float* v = sv + row * 64;
        const int* id = sidx + row * 64;
        unsigned long long used = 0;
        #pragma unroll
        for (int p = 0; p < NCAND; ++p) {
            float best = -FLT_MAX; int besti = 0x7fffffff; int bs = 0;
            for (int s = 0; s < 64; ++s) {
                if (!((used >> s) & 1ull)) {
                    float vv = v[s]; int ii = id[s];
                    if (vv > best || (vv == best && ii < besti)) {
                        best = vv; besti = ii; bs = s;
                    }
                }
            }
            used |= 1ull << bs;
            g_cand[(qbase + row) * NCAND + p] = besti;
        }
    }
}

// ---------------- fp32 rescore + softmax + gather ----------------
__global__ __launch_bounds__(256, 4) void rescore_kernel(const float* __restrict__ q,
                                                         const float* __restrict__ keys,
                                                         const float* __restrict__ values,
                                                         float* __restrict__ out) {
    const int b = blockIdx.x;
    const int tid = threadIdx.x, wid = tid >> 5, lane = tid & 31;
    __shared__ float ssim[NCAND];
    __shared__ int sidx[NCAND];
    __shared__ float sw[4];
    __shared__ int si[4];

    const int cand = g_cand[b * NCAND + wid];   // 8 warps, one candidate each
    const float4* q4 = reinterpret_cast<const float4*>(q) + (size_t)b * (ND / 4);
    const float4* k4 = reinterpret_cast<const float4*>(keys) + (size_t)cand * (ND / 4);
    float acc = 0.0f;
    #pragma unroll 4
    for (int u = 0; u < 8; ++u) {
        float4 a = q4[u * 32 + lane];
        float4 c = k4[u * 32 + lane];
        acc += a.x * c.x + a.y * c.y + a.z * c.z + a.w * c.w;
    }
    #pragma unroll
    for (int o = 16; o; o >>= 1) acc += __shfl_xor_sync(0xffffffffu, acc, o);
    if (lane == 0) { ssim[wid] = acc * g_qinv[b] * g_kinv[cand]; sidx[wid] = cand; }
    __syncthreads();

    if (tid == 0) {
        float v[NCAND]; int id[NCAND];
        #pragma unroll
        for (int s = 0; s < NCAND; ++s) { v[s] = ssim[s]; id[s] = sidx[s]; }
        float bv[4]; int bi[4]; unsigned used = 0;
        #pragma unroll
        for (int p = 0; p < 4; ++p) {
            float best = -FLT_MAX; int besti = 0x7fffffff; int bs = 0;
            #pragma unroll
            for (int s = 0; s < NCAND; ++s) {
                if (!((used >> s) & 1u)) {
                    if (v[s] > best || (v[s] == best && id[s] < besti)) {
                        best = v[s]; besti = id[s]; bs = s;
                    }
                }
            }
            used |= 1u << bs; bv[p] = best; bi[p] = besti;
        }
        float e[4], sum = 0.0f;
        #pragma unroll
        for (int jx = 0; jx < 4; ++jx) { e[jx] = expf(bv[jx] - bv[0]); sum += e[jx]; }
        float inv = 1.0f / sum;
        #pragma unroll
        for (int jx = 0; jx < 4; ++jx) { sw[jx] = e[jx] * inv; si[jx] = bi[jx]; }
    }
    __syncthreads();

    const float w0 = sw[0], w1 = sw[1], w2 = sw[2], w3 = sw[3];
    const int i0 = si[0], i1 = si[1], i2 = si[2], i3 = si[3];
    const float4* v4 = reinterpret_cast<const float4*>(values);
    float4 a = v4[(size_t)i0 * (ND / 4) + tid];
    float4 bb = v4[(size_t)i1 * (ND / 4) + tid];
    float4 c = v4[(size_t)i2 * (ND / 4) + tid];
    float4 d = v4[(size_t)i3 * (ND / 4) + tid];
    float4 r;
    r.x = fmaf(w3, d.x, fmaf(w2, c.x, fmaf(w1, bb.x, w0 * a.x)));
    r.y = fmaf(w3, d.y, fmaf(w2, c.y, fmaf(w1, bb.y, w0 * a.y)));
    r.z = fmaf(w3, d.z, fmaf(w2, c.z, fmaf(w1, bb.z, w0 * a.z)));
    r.w = fmaf(w3, d.w, fmaf(w2, c.w, fmaf(w1, bb.w, w0 * a.w)));
    reinterpret_cast<float4*>(out)[(size_t)b * (ND / 4) + tid] = r;
}

// ---------------- launch ----------------
extern "C" void kernel_launch(void* const* d_in, const int* in_sizes, int n_in,
                              void* d_out, int out_size) {
    const float* query = (const float*)d_in[0];
    const float* keys = (const float*)d_in[1];
    const float* values = (const float*)d_in[2];
    // d_in[3] = k, fixed at 4 for this shape.

    cudaFuncSetAttribute(simtopk_kernel, cudaFuncAttributeMaxDynamicSharedMemorySize,
                         SMEM_BYTES);
    norm_kernel<<<NB, 256>>>(query, 0);
    norm_kernel<<<NKEY, 256>>>(keys, 1);
    simtopk_kernel<<<NB / BM, THREADS, SMEM_BYTES>>>();
    rescore_kernel<<<NB, 256>>>(query, keys, values, (float*)d_out);
}

// round 5
// speedup vs baseline: 1.6635x; 1.6635x over previous
#include <cuda_runtime.h>
#include <cuda_bf16.h>
#include <cfloat>
#include <stdint.h>
#include <math.h>

#define NB 16384
#define NKEY 8192
#define ND 1024
#define BM 128
#define BN 256
#define BK 64
#define STAGES 4
#define NTILE (NKEY / BN)          // 32 key tiles
#define KSTEPS (ND / BK)           // 16 k-steps per tile
#define NSTEP (NTILE * KSTEPS)     // 512
#define NCAND 8
#define THREADS 512

#define ROWB 144                   // 128B data + 16B pad
#define A_BYTES (BM * ROWB)        // 18432
#define B_BYTES (BN * ROWB)        // 36864
#define STAGE_BYTES (A_BYTES + B_BYTES)   // 55296
#define SMEM_BYTES (STAGES * STAGE_BYTES) // 221184 (fits 227KB; 1 CTA/SM)

// ---------------- scratch ----------------
__device__ __nv_bfloat16 g_qn16[(size_t)NB * ND];
__device__ __nv_bfloat16 g_kn16[(size_t)NKEY * ND];
__device__ float g_qinv[NB];
__device__ float g_kinv[NKEY];
__device__ int   g_cand[NB * NCAND];

// ---------------- helpers ----------------
static __device__ __forceinline__ uint32_t smem_u32(const void* p) {
    return (uint32_t)__cvta_generic_to_shared(p);
}
static __device__ __forceinline__ void cp16(uint32_t dst, const void* src) {
    asm volatile("cp.async.cg.shared.global [%0], [%1], 16;" :: "r"(dst), "l"(src));
}
static __device__ __forceinline__ void cp_commit() {
    asm volatile("cp.async.commit_group;" ::: "memory");
}
static __device__ __forceinline__ void cp_wait2() {
    asm volatile("cp.async.wait_group 2;" ::: "memory");
}
static __device__ __forceinline__ void ldm_x4(uint32_t* r, uint32_t a) {
    asm volatile("ldmatrix.sync.aligned.m8n8.x4.shared.b16 {%0,%1,%2,%3}, [%4];"
                 : "=r"(r[0]), "=r"(r[1]), "=r"(r[2]), "=r"(r[3]) : "r"(a));
}
static __device__ __forceinline__ void mma16816(float* d, const uint32_t* a,
                                                const uint32_t* b) {
    asm volatile(
        "mma.sync.aligned.m16n8k16.row.col.f32.bf16.bf16.f32 "
        "{%0,%1,%2,%3}, {%4,%5,%6,%7}, {%8,%9}, {%0,%1,%2,%3};"
        : "+f"(d[0]), "+f"(d[1]), "+f"(d[2]), "+f"(d[3])
        : "r"(a[0]), "r"(a[1]), "r"(a[2]), "r"(a[3]), "r"(b[0]), "r"(b[1]));
}

// ---------------- normalize -> bf16 (+ inverse norms) ----------------
__global__ void norm_kernel(const float* __restrict__ in, int which) {
    __nv_bfloat16* out = which ? g_kn16 : g_qn16;
    float* invp = which ? g_kinv : g_qinv;
    int row = blockIdx.x;
    int t = threadIdx.x;  // 256 threads, one float4 each
    float4 v = reinterpret_cast<const float4*>(in)[(size_t)row * (ND / 4) + t];
    float ss = v.x * v.x + v.y * v.y + v.z * v.z + v.w * v.w;
    #pragma unroll
    for (int o = 16; o; o >>= 1) ss += __shfl_xor_sync(0xffffffffu, ss, o);
    __shared__ float wsum[8];
    if ((t & 31) == 0) wsum[t >> 5] = ss;
    __syncthreads();
    float tot = 0.0f;
    #pragma unroll
    for (int i = 0; i < 8; ++i) tot += wsum[i];
    float inv = 1.0f / fmaxf(sqrtf(tot), 1e-12f);
    if (t == 0) invp[row] = inv;
    union { __nv_bfloat162 h2[2]; uint2 u; } pk;
    pk.h2[0] = __floats2bfloat162_rn(v.x * inv, v.y * inv);
    pk.h2[1] = __floats2bfloat162_rn(v.z * inv, v.w * inv);
    reinterpret_cast<uint2*>(out)[(size_t)row * (ND / 4) + t] = pk.u;
}

// ---------------- top-4 insert ----------------
static __device__ __forceinline__ void top4_insert(float* tv, int* ti, float v, int idx) {
    if (v > tv[3]) {
        tv[3] = v; ti[3] = idx;
        #pragma unroll
        for (int s = 3; s > 0; --s) {
            if (tv[s] > tv[s - 1]) {
                float tf = tv[s]; tv[s] = tv[s - 1]; tv[s - 1] = tf;
                int tn = ti[s]; ti[s] = ti[s - 1]; ti[s - 1] = tn;
            }
        }
    }
}

// ---------------- bf16 sim GEMM (mma.sync) + streaming top-4/slice ----------------
__global__ __launch_bounds__(THREADS, 1) void simtopk_kernel() {
    extern __shared__ char dynsmem[];
    const uint32_t sbase = smem_u32(dynsmem);
    const int tid = threadIdx.x;
    const int wid = tid >> 5, lane = tid & 31;
    const int warp_m = wid & 3;     // 0..3 -> rows warp_m*32
    const int warp_n = wid >> 2;    // 0..3 -> cols warp_n*64
    const int qbase = blockIdx.x * BM;

    float acc[2][8][4];
    float tv[4][4]; int ti[4][4];
    #pragma unroll
    for (int mf = 0; mf < 2; ++mf)
        #pragma unroll
        for (int nf = 0; nf < 8; ++nf)
            #pragma unroll
            for (int e = 0; e < 4; ++e) acc[mf][nf][e] = 0.0f;
    #pragma unroll
    for (int r = 0; r < 4; ++r)
        #pragma unroll
        for (int e = 0; e < 4; ++e) { tv[r][e] = -FLT_MAX; ti[r][e] = 0; }

    auto issue_loads = [&](int j) {
        const int stage = j & 3;
        const int ks = j & (KSTEPS - 1), kt = j / KSTEPS;
        const int kcol = ks * BK;
        const uint32_t aS = sbase + stage * STAGE_BYTES;
        const uint32_t bS = aS + A_BYTES;
        #pragma unroll
        for (int u = 0; u < 2; ++u) {   // A: 128 rows x 8 chunks of 16B = 1024
            int idx = tid + 512 * u;
            int row = idx >> 3, c = idx & 7;
            cp16(aS + row * ROWB + c * 16,
                 g_qn16 + (size_t)(qbase + row) * ND + kcol + c * 8);
        }
        #pragma unroll
        for (int u = 0; u < 4; ++u) {   // B: 256 rows x 8 chunks = 2048
            int idx = tid + 512 * u;
            int row = idx >> 3, c = idx & 7;
            cp16(bS + row * ROWB + c * 16,
                 g_kn16 + (size_t)(kt * BN + row) * ND + kcol + c * 8);
        }
    };

    #pragma unroll
    for (int j = 0; j < STAGES - 1; ++j) { issue_loads(j); cp_commit(); }

    for (int i = 0; i < NSTEP; ++i) {
        cp_wait2();
        __syncthreads();     // stage i visible; stage i-1 free for overwrite
        if (i + 3 < NSTEP) issue_loads(i + 3);
        cp_commit();

        const uint32_t aS = sbase + (i & 3) * STAGE_BYTES;
        const uint32_t bS = aS + A_BYTES;
        const uint32_t aAddr = aS + (warp_m * 32 + (lane & 15)) * ROWB + (lane >> 4) * 16;
        const uint32_t bAddr = bS + (warp_n * 64 + (lane & 7) + (lane >> 4) * 8) * ROWB
                               + ((lane >> 3) & 1) * 16;
        #pragma unroll
        for (int kf = 0; kf < 4; ++kf) {
            uint32_t af[2][4];
            ldm_x4(af[0], aAddr + kf * 32);
            ldm_x4(af[1], aAddr + 16 * ROWB + kf * 32);
            #pragma unroll
            for (int ng = 0; ng < 4; ++ng) {
                uint32_t bf[4];
                ldm_x4(bf, bAddr + ng * 16 * ROWB + kf * 32);
                mma16816(acc[0][2 * ng],     af[0], bf + 0);
                mma16816(acc[0][2 * ng + 1], af[0], bf + 2);
                mma16816(acc[1][2 * ng],     af[1], bf + 0);
                mma16816(acc[1][2 * ng + 1], af[1], bf + 2);
            }
        }

        if ((i & (KSTEPS - 1)) == KSTEPS - 1) {  // key tile done: fold top-4/slice
            const int cb = (i / KSTEPS) * BN + warp_n * 64 + (lane & 3) * 2;
            #pragma unroll
            for (int mf = 0; mf < 2; ++mf)
                #pragma unroll
                for (int nf = 0; nf < 8; ++nf) {
                    float* a4 = acc[mf][nf];
                    const int c0 = cb + nf * 8;
                    top4_insert(tv[mf * 2],     ti[mf * 2],     a4[0], c0);
                    top4_insert(tv[mf * 2],     ti[mf * 2],     a4[1], c0 + 1);
                    top4_insert(tv[mf * 2 + 1], ti[mf * 2 + 1], a4[2], c0);
                    top4_insert(tv[mf * 2 + 1], ti[mf * 2 + 1], a4[3], c0 + 1);
                    a4[0] = a4[1] = a4[2] = a4[3] = 0.0f;
                }
        }
    }

    // ---------------- merge: 16 slices x top-4 -> top-8 per row ----------------
    __syncthreads();
    float* sv = reinterpret_cast<float*>(dynsmem);            // [128][16][4]
    int* sidx = reinterpret_cast<int*>(dynsmem + 32768);      // [128][16][4]
    #pragma unroll
    for (int rp = 0; rp < 4; ++rp) {
        int row = warp_m * 32 + (rp >> 1) * 16 + (rp & 1) * 8 + (lane >> 2);
        int slice = warp_n * 4 + (lane & 3);
        #pragma unroll
        for (int e = 0; e < 4; ++e) {
            sv[(row * 16 + slice) * 4 + e] = tv[rp][e];
            sidx[(row * 16 + slice) * 4 + e] = ti[rp][e];
        }
    }
    __syncthreads();
    if (tid < BM) {
        const int row = tid;
        const float* v = sv + row * 64;
        const int* id = sidx + row * 64;
        unsigned long long used = 0;
        #pragma unroll
        for (int p = 0; p < NCAND; ++p) {
            float best = -FLT_MAX; int besti = 0x7fffffff; int bs = 0;
            for (int s = 0; s < 64; ++s) {
                if (!((used >> s) & 1ull)) {
                    float vv = v[s]; int ii = id[s];
                    if (vv > best || (vv == best && ii < besti)) {
                        best = vv; besti = ii; bs = s;
                    }
                }
            }
            used |= 1ull << bs;
            g_cand[(qbase + row) * NCAND + p] = besti;
        }
    }
}

// ---------------- fp32 rescore + softmax + gather ----------------
__global__ __launch_bounds__(256, 4) void rescore_kernel(const float* __restrict__ q,
                                                         const float* __restrict__ keys,
                                                         const float* __restrict__ values,
                                                         float* __restrict__ out) {
    const int b = blockIdx.x;
    const int tid = threadIdx.x, wid = tid >> 5, lane = tid & 31;
    __shared__ float ssim[NCAND];
    __shared__ int sidx[NCAND];
    __shared__ float sw[4];
    __shared__ int si[4];

    const int cand = g_cand[b * NCAND + wid];   // 8 warps, one candidate each
    const float4* q4 = reinterpret_cast<const float4*>(q) + (size_t)b * (ND / 4);
    const float4* k4 = reinterpret_cast<const float4*>(keys) + (size_t)cand * (ND / 4);
    float acc = 0.0f;
    #pragma unroll 4
    for (int u = 0; u < 8; ++u) {
        float4 a = q4[u * 32 + lane];
        float4 c = k4[u * 32 + lane];
        acc += a.x * c.x + a.y * c.y + a.z * c.z + a.w * c.w;
    }
    #pragma unroll
    for (int o = 16; o; o >>= 1) acc += __shfl_xor_sync(0xffffffffu, acc, o);
    if (lane == 0) { ssim[wid] = acc * g_qinv[b] * g_kinv[cand]; sidx[wid] = cand; }
    __syncthreads();

    if (tid == 0) {
        float v[NCAND]; int id[NCAND];
        #pragma unroll
        for (int s = 0; s < NCAND; ++s) { v[s] = ssim[s]; id[s] = sidx[s]; }
        float bv[4]; int bi[4]; unsigned used = 0;
        #pragma unroll
        for (int p = 0; p < 4; ++p) {
            float best = -FLT_MAX; int besti = 0x7fffffff; int bs = 0;
            #pragma unroll
            for (int s = 0; s < NCAND; ++s) {
                if (!((used >> s) & 1u)) {
                    if (v[s] > best || (v[s] == best && id[s] < besti)) {
                        best = v[s]; besti = id[s]; bs = s;
                    }
                }
            }
            used |= 1u << bs; bv[p] = best; bi[p] = besti;
        }
        float e[4], sum = 0.0f;
        #pragma unroll
        for (int jx = 0; jx < 4; ++jx) { e[jx] = expf(bv[jx] - bv[0]); sum += e[jx]; }
        float inv = 1.0f / sum;
        #pragma unroll
        for (int jx = 0; jx < 4; ++jx) { sw[jx] = e[jx] * inv; si[jx] = bi[jx]; }
    }
    __syncthreads();

    const float w0 = sw[0], w1 = sw[1], w2 = sw[2], w3 = sw[3];
    const int i0 = si[0], i1 = si[1], i2 = si[2], i3 = si[3];
    const float4* v4 = reinterpret_cast<const float4*>(values);
    float4 a = v4[(size_t)i0 * (ND / 4) + tid];
    float4 bb = v4[(size_t)i1 * (ND / 4) + tid];
    float4 c = v4[(size_t)i2 * (ND / 4) + tid];
    float4 d = v4[(size_t)i3 * (ND / 4) + tid];
    float4 r;
    r.x = fmaf(w3, d.x, fmaf(w2, c.x, fmaf(w1, bb.x, w0 * a.x)));
    r.y = fmaf(w3, d.y, fmaf(w2, c.y, fmaf(w1, bb.y, w0 * a.y)));
    r.z = fmaf(w3, d.z, fmaf(w2, c.z, fmaf(w1, bb.z, w0 * a.z)));
    r.w = fmaf(w3, d.w, fmaf(w2, c.w, fmaf(w1, bb.w, w0 * a.w)));
    reinterpret_cast<float4*>(out)[(size_t)b * (ND / 4) + tid] = r;
}

// ---------------- launch ----------------
extern "C" void kernel_launch(void* const* d_in, const int* in_sizes, int n_in,
                              void* d_out, int out_size) {
    const float* query = (const float*)d_in[0];
    const float* keys = (const float*)d_in[1];
    const float* values = (const float*)d_in[2];
    // d_in[3] = k, fixed at 4 for this shape.

    cudaFuncSetAttribute(simtopk_kernel, cudaFuncAttributeMaxDynamicSharedMemorySize,
                         SMEM_BYTES);
    norm_kernel<<<NB, 256>>>(query, 0);
    norm_kernel<<<NKEY, 256>>>(keys, 1);
    simtopk_kernel<<<NB / BM, THREADS, SMEM_BYTES>>>();
    rescore_kernel<<<NB, 256>>>(query, keys, values, (float*)d_out);
}